// round 1
// baseline (speedup 1.0000x reference)
#include <cuda_runtime.h>
#include <cuda_bf16.h>
#include <math.h>

// Problem dims (fixed by the dataset)
#define BATCH 8
#define CCH   512          // channels c
#define NQ    4096         // H*W query length
#define TLEN  256          // context tokens
#define CDIM  768          // context channels
#define HID   512          // heads*dim_head
#define NHEAD 8
#define DHEAD 64

// Scratch (allocation-free rule: __device__ globals)
__device__ float g_q  [(long)BATCH * HID * NQ];          // [b][o][n]      64 MB
__device__ float g_kv [(long)BATCH * 2 * HID * TLEN];    // [b][o][t]       8 MB
__device__ float g_sim[(long)BATCH * NHEAD * NQ * TLEN]; // [b][h][i][j]  256 MB
__device__ float g_out[(long)BATCH * HID * NQ];          // [b][hd][n]     64 MB

#define BM 64
#define BN 64
#define BK 16
#define PAD 4

// Generic strided batched GEMM:
//   C[z][m][n] = alpha * sum_k A(m,k) * B(k,n)  (+ bias[m])
// A element: A + offA(z) + m*sAm + k*sAk
// B element: B + offB(z) + k*sBk + n*sBn
// C element: C + offC(z) + m*ldc + n           (row-major)
// off*(z) = (z/zdiv)*s*1 + (z%zdiv)*s*2
__global__ __launch_bounds__(256) void gemm_kernel(
    const float* __restrict__ A, const float* __restrict__ B,
    float* __restrict__ C, const float* __restrict__ bias,
    int M, int N, int K,
    int sAm, int sAk, int sBk, int sBn, int ldc,
    long sA1, long sA2, long sB1, long sB2, long sC1, long sC2,
    int zdiv, float alpha)
{
    __shared__ float As[BK][BM + PAD];
    __shared__ float Bs[BK][BN + PAD];

    const int z  = blockIdx.z;
    const int z1 = z / zdiv, z2 = z % zdiv;
    A += z1 * sA1 + z2 * sA2;
    B += z1 * sB1 + z2 * sB2;
    C += z1 * sC1 + z2 * sC2;

    const int n0 = blockIdx.x * BN;
    const int m0 = blockIdx.y * BM;
    const int tid = threadIdx.x;
    const int tx = tid & 15;
    const int ty = tid >> 4;

    float acc[4][4] = {};

    for (int k0 = 0; k0 < K; k0 += BK) {
        // ---- load A tile (pick mapping so the unit-stride dim is contiguous across tid)
        if (sAm == 1) {
            #pragma unroll
            for (int r = 0; r < 4; r++) {
                int idx = tid + r * 256;
                int m = idx & (BM - 1);
                int kk = idx >> 6;            // idx / BM
                As[kk][m] = A[(long)(m0 + m) * sAm + (long)(k0 + kk) * sAk];
            }
        } else { // sAk == 1
            #pragma unroll
            for (int r = 0; r < 4; r++) {
                int idx = tid + r * 256;
                int kk = idx & (BK - 1);
                int m = idx >> 4;             // idx / BK
                As[kk][m] = A[(long)(m0 + m) * sAm + (long)(k0 + kk)];
            }
        }
        // ---- load B tile
        if (sBn == 1) {
            #pragma unroll
            for (int r = 0; r < 4; r++) {
                int idx = tid + r * 256;
                int n = idx & (BN - 1);
                int kk = idx >> 6;
                Bs[kk][n] = B[(long)(k0 + kk) * sBk + (long)(n0 + n)];
            }
        } else { // sBk == 1
            #pragma unroll
            for (int r = 0; r < 4; r++) {
                int idx = tid + r * 256;
                int kk = idx & (BK - 1);
                int n = idx >> 4;
                Bs[kk][n] = B[(long)(k0 + kk) + (long)(n0 + n) * sBn];
            }
        }
        __syncthreads();

        #pragma unroll
        for (int kk = 0; kk < BK; kk++) {
            float4 av = *(const float4*)&As[kk][ty * 4];
            float4 bv = *(const float4*)&Bs[kk][tx * 4];
            float a[4] = {av.x, av.y, av.z, av.w};
            float b[4] = {bv.x, bv.y, bv.z, bv.w};
            #pragma unroll
            for (int i = 0; i < 4; i++)
                #pragma unroll
                for (int j = 0; j < 4; j++)
                    acc[i][j] = fmaf(a[i], b[j], acc[i][j]);
        }
        __syncthreads();
    }

    #pragma unroll
    for (int i = 0; i < 4; i++) {
        int m = m0 + ty * 4 + i;
        float bv = bias ? bias[m] : 0.0f;
        float4 o;
        o.x = acc[i][0] * alpha + bv;
        o.y = acc[i][1] * alpha + bv;
        o.z = acc[i][2] * alpha + bv;
        o.w = acc[i][3] * alpha + bv;
        *(float4*)&C[(long)m * ldc + n0 + tx * 4] = o;
    }
}

// Row softmax over last dim = TLEN (256). One warp per row, 8 elems per lane.
__global__ __launch_bounds__(256) void softmax_kernel(float* __restrict__ sim, int rows)
{
    int gwarp = (blockIdx.x * blockDim.x + threadIdx.x) >> 5;
    int lane = threadIdx.x & 31;
    if (gwarp >= rows) return;
    float* row = sim + (long)gwarp * TLEN;

    float v[8];
    float mx = -INFINITY;
    #pragma unroll
    for (int i = 0; i < 8; i++) {
        v[i] = row[lane + 32 * i];
        mx = fmaxf(mx, v[i]);
    }
    #pragma unroll
    for (int o = 16; o; o >>= 1) mx = fmaxf(mx, __shfl_xor_sync(0xffffffffu, mx, o));
    float s = 0.0f;
    #pragma unroll
    for (int i = 0; i < 8; i++) {
        v[i] = __expf(v[i] - mx);
        s += v[i];
    }
    #pragma unroll
    for (int o = 16; o; o >>= 1) s += __shfl_xor_sync(0xffffffffu, s, o);
    float inv = 1.0f / s;
    #pragma unroll
    for (int i = 0; i < 8; i++) row[lane + 32 * i] = v[i] * inv;
}

extern "C" void kernel_launch(void* const* d_in, const int* in_sizes, int n_in,
                              void* d_out, int out_size)
{
    const float* x    = (const float*)d_in[0];   // [b, c, H, W]     b*c*4096
    const float* ctx  = (const float*)d_in[1];   // [b, t, cdim]
    const float* Wq   = (const float*)d_in[2];   // [hid, c]
    const float* Wkv  = (const float*)d_in[3];   // [2*hid, cdim]
    const float* Wout = (const float*)d_in[4];   // [c, hid]
    const float* bout = (const float*)d_in[5];   // [c]
    float* y = (float*)d_out;                    // [b, c, H, W]

    float *q, *kv, *sim, *outb;
    cudaGetSymbolAddress((void**)&q,    g_q);
    cudaGetSymbolAddress((void**)&kv,   g_kv);
    cudaGetSymbolAddress((void**)&sim,  g_sim);
    cudaGetSymbolAddress((void**)&outb, g_out);

    const float scale = 0.125f; // 64^-0.5
    dim3 blk(256);

    // 1) q[b][o][n] = scale * Wq[o][c] * x[b][c][n]     M=512 N=4096 K=512
    gemm_kernel<<<dim3(NQ / BN, HID / BM, BATCH), blk>>>(
        Wq, x, q, nullptr,
        HID, NQ, CCH,
        /*sAm*/ CCH, /*sAk*/ 1, /*sBk*/ NQ, /*sBn*/ 1, /*ldc*/ NQ,
        0, 0, (long)CCH * NQ, 0, (long)HID * NQ, 0,
        1, scale);

    // 2) kv[b][o][t] = Wkv[o][c] * ctx[b][t][c]         M=1024 N=256 K=768
    gemm_kernel<<<dim3(TLEN / BN, (2 * HID) / BM, BATCH), blk>>>(
        Wkv, ctx, kv, nullptr,
        2 * HID, TLEN, CDIM,
        /*sAm*/ CDIM, /*sAk*/ 1, /*sBk*/ 1, /*sBn*/ CDIM, /*ldc*/ TLEN,
        0, 0, (long)TLEN * CDIM, 0, (long)2 * HID * TLEN, 0,
        1, 1.0f);

    // 3) sim[b][h][i][j] = q[b][h*64+d][i] * k[b][h*64+d][j]   z=b*8+h, M=4096 N=256 K=64
    gemm_kernel<<<dim3(TLEN / BN, NQ / BM, BATCH * NHEAD), blk>>>(
        q, kv, sim, nullptr,
        NQ, TLEN, DHEAD,
        /*sAm*/ 1, /*sAk*/ NQ, /*sBk*/ TLEN, /*sBn*/ 1, /*ldc*/ TLEN,
        (long)HID * NQ, (long)DHEAD * NQ,
        (long)2 * HID * TLEN, (long)DHEAD * TLEN,
        (long)NHEAD * NQ * TLEN, (long)NQ * TLEN,
        NHEAD, 1.0f);

    // 4) softmax over j (in place on sim)
    {
        int rows = BATCH * NHEAD * NQ; // 262144
        softmax_kernel<<<rows / 8, blk>>>(sim, rows);
    }

    // 5) out[b][h*64+d][i] = sum_j v[b][512+h*64+d][j] * attn[b][h][i][j]
    //    M=64 N=4096 K=256
    gemm_kernel<<<dim3(NQ / BN, DHEAD / BM, BATCH * NHEAD), blk>>>(
        kv + (long)HID * TLEN, sim, outb, nullptr,
        DHEAD, NQ, TLEN,
        /*sAm*/ TLEN, /*sAk*/ 1, /*sBk*/ 1, /*sBn*/ TLEN, /*ldc*/ NQ,
        (long)2 * HID * TLEN, (long)DHEAD * TLEN,
        (long)NHEAD * NQ * TLEN, (long)NQ * TLEN,
        (long)HID * NQ, (long)DHEAD * NQ,
        NHEAD, 1.0f);

    // 6) y[b][o][n] = Wout[o][c] * out[b][c][n] + bout[o]   M=512 N=4096 K=512
    gemm_kernel<<<dim3(NQ / BN, CCH / BM, BATCH), blk>>>(
        Wout, outb, y, bout,
        CCH, NQ, HID,
        /*sAm*/ HID, /*sAk*/ 1, /*sBk*/ NQ, /*sBn*/ 1, /*ldc*/ NQ,
        0, 0, (long)HID * NQ, 0, (long)CCH * NQ, 0,
        1, 1.0f);
}

// round 3
// speedup vs baseline: 2.3085x; 2.3085x over previous
#include <cuda_runtime.h>
#include <cuda_bf16.h>
#include <cstdint>
#include <math.h>

// ---------------- problem dims ----------------
#define BATCH 8
#define CCH   512
#define NQ    4096
#define TLEN  256
#define CDIM  768
#define HID   512
#define NHEAD 8
#define DHEAD 64

// ---------------- scratch ----------------
__device__ float g_q  [(long)BATCH * HID * NQ];
__device__ float g_kv [(long)BATCH * 2 * HID * TLEN];
__device__ float g_sim[(long)BATCH * NHEAD * NQ * TLEN];
__device__ float g_out[(long)BATCH * HID * NQ];

__device__ __forceinline__ uint32_t f2tf32(float x) {
    uint32_t u;
    asm("cvt.rna.tf32.f32 %0, %1;" : "=r"(u) : "f"(x));
    return u;
}
__device__ __forceinline__ float tf32f(float x) { return __uint_as_float(f2tf32(x)); }

__device__ __forceinline__ void mma_tf32(float* d, const float* a, const float* b) {
    asm volatile(
        "mma.sync.aligned.m16n8k8.row.col.f32.tf32.tf32.f32 "
        "{%0,%1,%2,%3}, {%4,%5,%6,%7}, {%8,%9}, {%0,%1,%2,%3};"
        : "+f"(d[0]), "+f"(d[1]), "+f"(d[2]), "+f"(d[3])
        : "r"(__float_as_uint(a[0])), "r"(__float_as_uint(a[1])),
          "r"(__float_as_uint(a[2])), "r"(__float_as_uint(a[3])),
          "r"(__float_as_uint(b[0])), "r"(__float_as_uint(b[1])));
}

// =====================================================================
// Tensor-core tf32 GEMM via mma.sync (base-ISA, works on compute_103):
//   C[z][m][n] = alpha * sum_k A(m,k) * B(k,n)  (+ bias[m])
// ADIR=1: A[m][k] k-contig (lda = row stride). ADIR=0: A[k][m] m-contig (lda = k-row stride).
// BDIR=1: B[n][k] k-contig (ldb = n-row stride). BDIR=0: B[k][n] n-contig (ldb = k-row stride).
// Tiles: BM x 128, BK=16. 8 warps. BM=128 -> warps 4x2 (each 32x64), BM=64 -> 2x4 (each 32x32).
// =====================================================================
template<int BM, int ADIR, int BDIR>
__global__ __launch_bounds__(256) void mma_gemm(
    const float* __restrict__ A, const float* __restrict__ B,
    float* __restrict__ C, const float* __restrict__ bias,
    int lda, int ldb, int ldc, int kTotal,
    long sA1, long sA2, long sB1, long sB2, long sC1, long sC2,
    int zdiv, float alpha)
{
    constexpr int BN = 128, BK = 16, RS = BK + 4;
    constexpr int WARPM = (BM == 128) ? 4 : 2;
    constexpr int WARPN = 8 / WARPM;
    constexpr int NSPAN = BN / WARPN;
    constexpr int NT = NSPAN / 8;     // 8-wide n tiles per warp
    constexpr int MT = 2;             // 16-tall m tiles per warp (span 32)
    constexpr int AR = (BM * 4) / 256; // float4 A loads per thread
    constexpr int BR = 2;              // float4 B loads per thread

    __shared__ float As[2][BM][RS];
    __shared__ float Bs[2][BN][RS];

    const int z  = blockIdx.z;
    const int z1 = z / zdiv, z2 = z % zdiv;
    A += z1 * sA1 + z2 * sA2;
    B += z1 * sB1 + z2 * sB2;
    C += z1 * sC1 + z2 * sC2;

    const int tid  = threadIdx.x;
    const int wid  = tid >> 5;
    const int lane = tid & 31;
    const int wm   = wid % WARPM;
    const int wn   = wid / WARPM;
    const int g    = lane >> 2;   // group id (0..7)
    const int t4   = lane & 3;    // thread in group

    const int m0 = blockIdx.y * BM;
    const int n0 = blockIdx.x * BN;
    const int mbase = wm * 32;
    const int nbase = wn * NSPAN;

    float acc[MT][NT][4];
    #pragma unroll
    for (int i = 0; i < MT; i++)
        #pragma unroll
        for (int j = 0; j < NT; j++)
            #pragma unroll
            for (int r = 0; r < 4; r++) acc[i][j][r] = 0.0f;

    float4 aR[AR], bR[BR];

    // ---- global load for k-chunk k0 into regs ----
    auto LOADG = [&](int k0) {
        #pragma unroll
        for (int r = 0; r < AR; r++) {
            int f = r * 256 + tid;
            if (ADIR) {
                int k4 = f & 3, m = f >> 2;
                aR[r] = *(const float4*)(A + (long)(m0 + m) * lda + k0 + k4 * 4);
            } else {
                int m4 = f & (BM / 4 - 1), kk = f / (BM / 4);
                aR[r] = *(const float4*)(A + (long)(k0 + kk) * lda + m0 + m4 * 4);
            }
        }
        #pragma unroll
        for (int r = 0; r < BR; r++) {
            int f = r * 256 + tid;
            if (BDIR) {
                int k4 = f & 3, n = f >> 2;
                bR[r] = *(const float4*)(B + (long)(n0 + n) * ldb + k0 + k4 * 4);
            } else {
                int n4 = f & 31, kk = f >> 5;
                bR[r] = *(const float4*)(B + (long)(k0 + kk) * ldb + n0 + n4 * 4);
            }
        }
    };
    // ---- store regs into smem stage s (tf32-rounded) ----
    auto STORES = [&](int s) {
        #pragma unroll
        for (int r = 0; r < AR; r++) {
            int f = r * 256 + tid;
            if (ADIR) {
                int k4 = f & 3, m = f >> 2;
                float* p = &As[s][m][k4 * 4];
                p[0] = tf32f(aR[r].x); p[1] = tf32f(aR[r].y);
                p[2] = tf32f(aR[r].z); p[3] = tf32f(aR[r].w);
            } else {
                int m4 = f & (BM / 4 - 1), kk = f / (BM / 4);
                As[s][m4 * 4 + 0][kk] = tf32f(aR[r].x);
                As[s][m4 * 4 + 1][kk] = tf32f(aR[r].y);
                As[s][m4 * 4 + 2][kk] = tf32f(aR[r].z);
                As[s][m4 * 4 + 3][kk] = tf32f(aR[r].w);
            }
        }
        #pragma unroll
        for (int r = 0; r < BR; r++) {
            int f = r * 256 + tid;
            if (BDIR) {
                int k4 = f & 3, n = f >> 2;
                float* p = &Bs[s][n][k4 * 4];
                p[0] = tf32f(bR[r].x); p[1] = tf32f(bR[r].y);
                p[2] = tf32f(bR[r].z); p[3] = tf32f(bR[r].w);
            } else {
                int n4 = f & 31, kk = f >> 5;
                Bs[s][n4 * 4 + 0][kk] = tf32f(bR[r].x);
                Bs[s][n4 * 4 + 1][kk] = tf32f(bR[r].y);
                Bs[s][n4 * 4 + 2][kk] = tf32f(bR[r].z);
                Bs[s][n4 * 4 + 3][kk] = tf32f(bR[r].w);
            }
        }
    };
    // ---- compute one BK=16 chunk from stage s ----
    auto COMPUTE = [&](int s) {
        #pragma unroll
        for (int ks = 0; ks < 2; ks++) {
            const int kof = ks * 8;
            float a[MT][4];
            #pragma unroll
            for (int mt = 0; mt < MT; mt++) {
                int mr = mbase + mt * 16 + g;
                a[mt][0] = As[s][mr][kof + t4];
                a[mt][1] = As[s][mr + 8][kof + t4];
                a[mt][2] = As[s][mr][kof + t4 + 4];
                a[mt][3] = As[s][mr + 8][kof + t4 + 4];
            }
            float b[NT][2];
            #pragma unroll
            for (int nt = 0; nt < NT; nt++) {
                int nr = nbase + nt * 8 + g;
                b[nt][0] = Bs[s][nr][kof + t4];
                b[nt][1] = Bs[s][nr][kof + t4 + 4];
            }
            #pragma unroll
            for (int mt = 0; mt < MT; mt++)
                #pragma unroll
                for (int nt = 0; nt < NT; nt++)
                    mma_tf32(acc[mt][nt], a[mt], b[nt]);
        }
    };

    const int niter = kTotal / BK;
    LOADG(0);
    STORES(0);
    __syncthreads();
    for (int it = 0; it < niter; it++) {
        if (it + 1 < niter) LOADG((it + 1) * BK);
        COMPUTE(it & 1);
        if (it + 1 < niter) {
            STORES((it + 1) & 1);
            __syncthreads();
        }
    }

    // ---- epilogue ----
    #pragma unroll
    for (int mt = 0; mt < MT; mt++) {
        int m = m0 + mbase + mt * 16 + g;
        float bv0 = bias ? bias[m] : 0.0f;
        float bv1 = bias ? bias[m + 8] : 0.0f;
        #pragma unroll
        for (int nt = 0; nt < NT; nt++) {
            int n = n0 + nbase + nt * 8 + t4 * 2;
            float2 lo = make_float2(acc[mt][nt][0] * alpha + bv0,
                                    acc[mt][nt][1] * alpha + bv0);
            float2 hi = make_float2(acc[mt][nt][2] * alpha + bv1,
                                    acc[mt][nt][3] * alpha + bv1);
            *(float2*)(C + (long)m * ldc + n) = lo;
            *(float2*)(C + (long)(m + 8) * ldc + n) = hi;
        }
    }
}

// ================= softmax =================
__global__ __launch_bounds__(256) void softmax_kernel(float* __restrict__ sim, int rows)
{
    int gwarp = (blockIdx.x * blockDim.x + threadIdx.x) >> 5;
    int lane = threadIdx.x & 31;
    if (gwarp >= rows) return;
    float* row = sim + (long)gwarp * TLEN;
    float v[8];
    float mx = -INFINITY;
    #pragma unroll
    for (int i = 0; i < 8; i++) {
        v[i] = row[lane + 32 * i];
        mx = fmaxf(mx, v[i]);
    }
    #pragma unroll
    for (int o = 16; o; o >>= 1) mx = fmaxf(mx, __shfl_xor_sync(0xffffffffu, mx, o));
    float s = 0.0f;
    #pragma unroll
    for (int i = 0; i < 8; i++) {
        v[i] = __expf(v[i] - mx);
        s += v[i];
    }
    #pragma unroll
    for (int o = 16; o; o >>= 1) s += __shfl_xor_sync(0xffffffffu, s, o);
    float inv = 1.0f / s;
    #pragma unroll
    for (int i = 0; i < 8; i++) row[lane + 32 * i] = v[i] * inv;
}

// ================= launch =================
extern "C" void kernel_launch(void* const* d_in, const int* in_sizes, int n_in,
                              void* d_out, int out_size)
{
    const float* x    = (const float*)d_in[0];
    const float* ctx  = (const float*)d_in[1];
    const float* Wq   = (const float*)d_in[2];
    const float* Wkv  = (const float*)d_in[3];
    const float* Wout = (const float*)d_in[4];
    const float* bout = (const float*)d_in[5];
    float* y = (float*)d_out;

    float *q, *kv, *sim, *outb;
    cudaGetSymbolAddress((void**)&q,    g_q);
    cudaGetSymbolAddress((void**)&kv,   g_kv);
    cudaGetSymbolAddress((void**)&sim,  g_sim);
    cudaGetSymbolAddress((void**)&outb, g_out);

    dim3 blk(256);

    // 1) q = 0.125 * Wq @ x      M=512,N=4096,K=512 per batch
    //    A=Wq[o][c] k-contig; B=x[c][n] n-contig
    mma_gemm<128, 1, 0><<<dim3(NQ / 128, CCH / 128, BATCH), blk>>>(
        Wq, x, q, nullptr, CCH, NQ, NQ, CCH,
        0, 0, (long)CCH * NQ, 0, (long)HID * NQ, 0, 1, 0.125f);

    // 2) kv = Wkv @ ctx^T        M=1024,N=256,K=768 per batch
    //    A=Wkv[o][c] k-contig; B=ctx[t][c] k-contig
    mma_gemm<128, 1, 1><<<dim3(TLEN / 128, (2 * HID) / 128, BATCH), blk>>>(
        Wkv, ctx, kv, nullptr, CDIM, CDIM, TLEN, CDIM,
        0, 0, (long)TLEN * CDIM, 0, (long)2 * HID * TLEN, 0, 1, 1.0f);

    // 3) sim[i][j] = sum_d q[d][i] k[d][j]   z=b*8+h, M=4096,N=256,K=64
    //    A=q[k=d][m=i] m-contig (lda=NQ); B=kv[k=d][n=j] n-contig (ldb=TLEN)
    mma_gemm<128, 0, 0><<<dim3(TLEN / 128, NQ / 128, BATCH * NHEAD), blk>>>(
        q, kv, sim, nullptr, NQ, TLEN, TLEN, DHEAD,
        (long)HID * NQ, (long)DHEAD * NQ,
        (long)2 * HID * TLEN, (long)DHEAD * TLEN,
        (long)NHEAD * NQ * TLEN, (long)NQ * TLEN,
        NHEAD, 1.0f);

    // 4) softmax over j
    softmax_kernel<<<(BATCH * NHEAD * NQ) / 8, blk>>>(sim, BATCH * NHEAD * NQ);

    // 5) out[d][i] = sum_j v[d][j] attn[i][j]   M=64,N=4096,K=256
    //    A=v[d][j] k-contig (lda=TLEN); B=attn[n=i][k=j] k-contig (ldb=TLEN)
    mma_gemm<64, 1, 1><<<dim3(NQ / 128, 1, BATCH * NHEAD), blk>>>(
        kv + (long)HID * TLEN, sim, outb, nullptr, TLEN, TLEN, NQ, TLEN,
        (long)2 * HID * TLEN, (long)DHEAD * TLEN,
        (long)NHEAD * NQ * TLEN, (long)NQ * TLEN,
        (long)HID * NQ, (long)DHEAD * NQ,
        NHEAD, 1.0f);

    // 6) y = Wout @ out + bout   M=512,N=4096,K=512 per batch
    mma_gemm<128, 1, 0><<<dim3(NQ / 128, CCH / 128, BATCH), blk>>>(
        Wout, outb, y, bout, HID, NQ, NQ, HID,
        0, 0, (long)HID * NQ, 0, (long)CCH * NQ, 0, 1, 1.0f);
}

// round 4
// speedup vs baseline: 3.9948x; 1.7304x over previous
#include <cuda_runtime.h>
#include <cuda_bf16.h>
#include <cstdint>
#include <math.h>

// ---------------- problem dims ----------------
#define BATCH 8
#define CCH   512
#define NQ    4096
#define TLEN  256
#define CDIM  768
#define HID   512
#define NHEAD 8
#define DHEAD 64

// ---------------- scratch ----------------
__device__ float g_q  [(long)BATCH * HID * NQ];       // [b][o=h*64+d][i]
__device__ float g_kv [(long)BATCH * 2 * HID * TLEN]; // [b][o][t]
__device__ float g_out[(long)BATCH * NQ * HID];       // [b][i][hd]  (i-major!)

__device__ __forceinline__ uint32_t f2tf32(float x) {
    uint32_t u;
    asm("cvt.rna.tf32.f32 %0, %1;" : "=r"(u) : "f"(x));
    return u;
}
__device__ __forceinline__ float tf32f(float x) { return __uint_as_float(f2tf32(x)); }

__device__ __forceinline__ void mma_tf32(float* d, const float* a, const float* b) {
    asm volatile(
        "mma.sync.aligned.m16n8k8.row.col.f32.tf32.tf32.f32 "
        "{%0,%1,%2,%3}, {%4,%5,%6,%7}, {%8,%9}, {%0,%1,%2,%3};"
        : "+f"(d[0]), "+f"(d[1]), "+f"(d[2]), "+f"(d[3])
        : "r"(__float_as_uint(a[0])), "r"(__float_as_uint(a[1])),
          "r"(__float_as_uint(a[2])), "r"(__float_as_uint(a[3])),
          "r"(__float_as_uint(b[0])), "r"(__float_as_uint(b[1])));
}

// =====================================================================
// tf32 mma.sync GEMM:  C[z][m][n] = alpha * A[m][k] * B(k,n) (+ bias[m])
// A[m][k] k-contig (lda). BDIR=1: B[n][k] k-contig. BDIR=0: B[k][n] n-contig.
// CTA tile 128x128, BK=16, 8 warps (4x2), warp tile 32x64.
// BDIR=0 stores B in native [k][n] smem layout (no transposed scatter ->
// conflict-free STS; frag reads take a 2-way conflict instead of 16-way).
// =====================================================================
template<int BDIR>
__global__ __launch_bounds__(256) void mma_gemm(
    const float* __restrict__ A, const float* __restrict__ B,
    float* __restrict__ C, const float* __restrict__ bias,
    int lda, int ldb, int ldc, int kTotal,
    long sB1, long sC1, float alpha)
{
    constexpr int BM = 128, BN = 128, BK = 16;
    constexpr int AS = BK + 4;                       // A row stride
    constexpr int BS1 = BK + 4;                      // BDIR=1: [n][k]
    constexpr int BS0 = BN + 4;                      // BDIR=0: [k][n]
    constexpr int BSIZE = BDIR ? BN * BS1 : BK * BS0;

    __shared__ float Asm[2][BM * AS];
    __shared__ float Bsm[2][BSIZE];

    const int z = blockIdx.z;
    B += (long)z * sB1;
    C += (long)z * sC1;

    const int tid  = threadIdx.x;
    const int wid  = tid >> 5;
    const int lane = tid & 31;
    const int wm   = wid & 3;
    const int wn   = wid >> 2;
    const int g    = lane >> 2;
    const int t4   = lane & 3;

    const int m0 = blockIdx.y * BM;
    const int n0 = blockIdx.x * BN;
    const int mb = wm * 32;
    const int nb = wn * 64;

    float acc[2][8][4];
    #pragma unroll
    for (int i = 0; i < 2; i++)
        #pragma unroll
        for (int j = 0; j < 8; j++)
            #pragma unroll
            for (int r = 0; r < 4; r++) acc[i][j][r] = 0.0f;

    float4 aR[2], bR[2];

    auto LOADG = [&](int k0) {
        #pragma unroll
        for (int r = 0; r < 2; r++) {
            int f = r * 256 + tid;
            int k4 = f & 3, m = f >> 2;
            aR[r] = *(const float4*)(A + (long)(m0 + m) * lda + k0 + k4 * 4);
        }
        #pragma unroll
        for (int r = 0; r < 2; r++) {
            int f = r * 256 + tid;
            if (BDIR) {
                int k4 = f & 3, n = f >> 2;
                bR[r] = *(const float4*)(B + (long)(n0 + n) * ldb + k0 + k4 * 4);
            } else {
                int n4 = f & 31, kk = f >> 5;
                bR[r] = *(const float4*)(B + (long)(k0 + kk) * ldb + n0 + n4 * 4);
            }
        }
    };
    auto STORES = [&](int s) {
        #pragma unroll
        for (int r = 0; r < 2; r++) {
            int f = r * 256 + tid;
            int k4 = f & 3, m = f >> 2;
            float4 c = make_float4(tf32f(aR[r].x), tf32f(aR[r].y), tf32f(aR[r].z), tf32f(aR[r].w));
            *(float4*)&Asm[s][m * AS + k4 * 4] = c;
        }
        #pragma unroll
        for (int r = 0; r < 2; r++) {
            int f = r * 256 + tid;
            float4 c = make_float4(tf32f(bR[r].x), tf32f(bR[r].y), tf32f(bR[r].z), tf32f(bR[r].w));
            if (BDIR) {
                int k4 = f & 3, n = f >> 2;
                *(float4*)&Bsm[s][n * BS1 + k4 * 4] = c;
            } else {
                int n4 = f & 31, kk = f >> 5;
                *(float4*)&Bsm[s][kk * BS0 + n4 * 4] = c;
            }
        }
    };
    auto COMPUTE = [&](int s) {
        #pragma unroll
        for (int ks = 0; ks < 2; ks++) {
            const int kof = ks * 8;
            float a[2][4];
            #pragma unroll
            for (int mt = 0; mt < 2; mt++) {
                const float* p = &Asm[s][(mb + mt * 16 + g) * AS + kof + t4];
                a[mt][0] = p[0];
                a[mt][1] = p[8 * AS];
                a[mt][2] = p[4];
                a[mt][3] = p[8 * AS + 4];
            }
            #pragma unroll
            for (int nt = 0; nt < 8; nt++) {
                float bb[2];
                if (BDIR) {
                    const float* p = &Bsm[s][(nb + nt * 8 + g) * BS1 + kof + t4];
                    bb[0] = p[0];
                    bb[1] = p[4];
                } else {
                    const float* p = &Bsm[s][(kof + t4) * BS0 + nb + nt * 8 + g];
                    bb[0] = p[0];
                    bb[1] = p[4 * BS0];
                }
                mma_tf32(acc[0][nt], a[0], bb);
                mma_tf32(acc[1][nt], a[1], bb);
            }
        }
    };

    const int niter = kTotal / BK;
    LOADG(0);
    STORES(0);
    __syncthreads();
    for (int it = 0; it < niter; it++) {
        if (it + 1 < niter) LOADG((it + 1) * BK);
        COMPUTE(it & 1);
        if (it + 1 < niter) {
            STORES((it + 1) & 1);
            __syncthreads();
        }
    }

    #pragma unroll
    for (int mt = 0; mt < 2; mt++) {
        int m = m0 + mb + mt * 16 + g;
        float bv0 = bias ? bias[m] : 0.0f;
        float bv1 = bias ? bias[m + 8] : 0.0f;
        #pragma unroll
        for (int nt = 0; nt < 8; nt++) {
            int n = n0 + nb + nt * 8 + t4 * 2;
            float2 lo = make_float2(acc[mt][nt][0] * alpha + bv0,
                                    acc[mt][nt][1] * alpha + bv0);
            float2 hi = make_float2(acc[mt][nt][2] * alpha + bv1,
                                    acc[mt][nt][3] * alpha + bv1);
            *(float2*)(C + (long)m * ldc + n) = lo;
            *(float2*)(C + (long)(m + 8) * ldc + n) = hi;
        }
    }
}

// =====================================================================
// Fused attention: per CTA = one head (b,h) x 128-query tile.
//   S = Q^T K (128x256, regs) -> softmax (row max/sum, 2-warp exchange)
//   -> P (unnormalized, tf32, smem; reuses dead Q/K region) -> O = P V
//   -> scale 1/sum -> store O[b][i][h*64+d]  (i-major layout).
// SMEM layouts: Q [d][i] s=132, K [d][j] s=260, V [d][j] s=260, P [i][j] s=260.
// =====================================================================
#define FQS 132
#define FKS 260
#define FPS 260
#define FOFFQ 0
#define FOFFK 8448
#define FOFFV 33280
#define FOFFP 0
#define FOFFRED 49920
#define FSM_FLOATS 50432
#define FSM_BYTES (FSM_FLOATS * 4)

__global__ __launch_bounds__(256, 1) void fused_attn(
    const float* __restrict__ q, const float* __restrict__ kv,
    float* __restrict__ out)
{
    extern __shared__ float sm[];
    const int z = blockIdx.y;            // b*8 + h
    const int b = z >> 3, h = z & 7;
    const int i0 = blockIdx.x * 128;
    const int tid = threadIdx.x;
    const int wid = tid >> 5, lane = tid & 31;
    const int wm = wid & 3, wn = wid >> 2;
    const int g = lane >> 2, t4 = lane & 3;

    const float* qp = q + (long)(b * HID + h * DHEAD) * NQ;     // [d][i]
    const float* kp = kv + (long)(b * 2 * HID + h * DHEAD) * TLEN;
    const float* vp = kp + (long)HID * TLEN;

    // ---- load Q (64x128), K,V (64x256) with tf32 rounding ----
    #pragma unroll
    for (int r = 0; r < 8; r++) {
        int f = r * 256 + tid;
        int i4 = f & 31, d = f >> 5;
        float4 v = *(const float4*)(qp + (long)d * NQ + i0 + i4 * 4);
        *(float4*)(sm + FOFFQ + d * FQS + i4 * 4) =
            make_float4(tf32f(v.x), tf32f(v.y), tf32f(v.z), tf32f(v.w));
    }
    #pragma unroll
    for (int r = 0; r < 16; r++) {
        int f = r * 256 + tid;
        int j4 = f & 63, d = f >> 6;
        float4 v = *(const float4*)(kp + d * TLEN + j4 * 4);
        *(float4*)(sm + FOFFK + d * FKS + j4 * 4) =
            make_float4(tf32f(v.x), tf32f(v.y), tf32f(v.z), tf32f(v.w));
        float4 w = *(const float4*)(vp + d * TLEN + j4 * 4);
        *(float4*)(sm + FOFFV + d * FKS + j4 * 4) =
            make_float4(tf32f(w.x), tf32f(w.y), tf32f(w.z), tf32f(w.w));
    }
    __syncthreads();

    const int MB = wm * 32, NB = wn * 128;

    // ---- S = Q^T K : warp tile 32 x 128 ----
    float acc[2][16][4];
    #pragma unroll
    for (int i = 0; i < 2; i++)
        #pragma unroll
        for (int j = 0; j < 16; j++)
            #pragma unroll
            for (int r = 0; r < 4; r++) acc[i][j][r] = 0.0f;

    #pragma unroll
    for (int kk = 0; kk < 8; kk++) {
        float a[2][4];
        #pragma unroll
        for (int mt = 0; mt < 2; mt++) {
            const float* p = sm + FOFFQ + (kk * 8 + t4) * FQS + MB + mt * 16 + g;
            a[mt][0] = p[0];
            a[mt][1] = p[8];
            a[mt][2] = p[4 * FQS];
            a[mt][3] = p[4 * FQS + 8];
        }
        #pragma unroll
        for (int nt = 0; nt < 16; nt++) {
            const float* p = sm + FOFFK + (kk * 8 + t4) * FKS + NB + nt * 8 + g;
            float bb[2] = { p[0], p[4 * FKS] };
            mma_tf32(acc[0][nt], a[0], bb);
            mma_tf32(acc[1][nt], a[1], bb);
        }
    }

    // ---- softmax: row max ----
    float* redm = sm + FOFFRED;        // [2][128]
    float* reds = sm + FOFFRED + 256;  // [2][128]
    float rmx[2][2], rsm[2][2], inv[2][2];
    #pragma unroll
    for (int mt = 0; mt < 2; mt++)
        #pragma unroll
        for (int u = 0; u < 2; u++) {
            float m = -INFINITY;
            #pragma unroll
            for (int nt = 0; nt < 16; nt++)
                m = fmaxf(m, fmaxf(acc[mt][nt][2 * u], acc[mt][nt][2 * u + 1]));
            m = fmaxf(m, __shfl_xor_sync(0xffffffffu, m, 1));
            m = fmaxf(m, __shfl_xor_sync(0xffffffffu, m, 2));
            if (t4 == 0) redm[wn * 128 + wm * 32 + mt * 16 + u * 8 + g] = m;
        }
    __syncthreads();   // redm visible; all S-phase smem reads complete
    #pragma unroll
    for (int mt = 0; mt < 2; mt++)
        #pragma unroll
        for (int u = 0; u < 2; u++) {
            int r = wm * 32 + mt * 16 + u * 8 + g;
            rmx[mt][u] = fmaxf(redm[r], redm[128 + r]);
            rsm[mt][u] = 0.0f;
        }

    // ---- exp, row-sum, stage unnormalized P to smem (overwrites Q/K) ----
    #pragma unroll
    for (int mt = 0; mt < 2; mt++) {
        int row = MB + mt * 16 + g;
        #pragma unroll
        for (int nt = 0; nt < 16; nt++) {
            int col = NB + nt * 8 + 2 * t4;
            float e0 = __expf(acc[mt][nt][0] - rmx[mt][0]);
            float e1 = __expf(acc[mt][nt][1] - rmx[mt][0]);
            float e2 = __expf(acc[mt][nt][2] - rmx[mt][1]);
            float e3 = __expf(acc[mt][nt][3] - rmx[mt][1]);
            rsm[mt][0] += e0 + e1;
            rsm[mt][1] += e2 + e3;
            *(float2*)(sm + FOFFP + (long)row * FPS + col) = make_float2(tf32f(e0), tf32f(e1));
            *(float2*)(sm + FOFFP + (long)(row + 8) * FPS + col) = make_float2(tf32f(e2), tf32f(e3));
        }
    }
    #pragma unroll
    for (int mt = 0; mt < 2; mt++)
        #pragma unroll
        for (int u = 0; u < 2; u++) {
            float s = rsm[mt][u];
            s += __shfl_xor_sync(0xffffffffu, s, 1);
            s += __shfl_xor_sync(0xffffffffu, s, 2);
            if (t4 == 0) reds[wn * 128 + wm * 32 + mt * 16 + u * 8 + g] = s;
        }
    __syncthreads();   // P staged, reds visible
    #pragma unroll
    for (int mt = 0; mt < 2; mt++)
        #pragma unroll
        for (int u = 0; u < 2; u++) {
            int r = wm * 32 + mt * 16 + u * 8 + g;
            inv[mt][u] = 1.0f / (reds[r] + reds[128 + r]);
        }

    // ---- O = P V : warp tile 32 x 32 over n=d(64) ----
    const int NB2 = wn * 32;
    float acco[2][4][4];
    #pragma unroll
    for (int i = 0; i < 2; i++)
        #pragma unroll
        for (int j = 0; j < 4; j++)
            #pragma unroll
            for (int r = 0; r < 4; r++) acco[i][j][r] = 0.0f;

    #pragma unroll 4
    for (int kk = 0; kk < 32; kk++) {
        float a[2][4];
        #pragma unroll
        for (int mt = 0; mt < 2; mt++) {
            const float* p = sm + FOFFP + (long)(MB + mt * 16 + g) * FPS + kk * 8 + t4;
            a[mt][0] = p[0];
            a[mt][1] = p[8 * FPS];
            a[mt][2] = p[4];
            a[mt][3] = p[8 * FPS + 4];
        }
        #pragma unroll
        for (int nto = 0; nto < 4; nto++) {
            const float* p = sm + FOFFV + (NB2 + nto * 8 + g) * FKS + kk * 8 + t4;
            float bb[2] = { p[0], p[4] };
            mma_tf32(acco[0][nto], a[0], bb);
            mma_tf32(acco[1][nto], a[1], bb);
        }
    }

    // ---- store O[b][i][h*64+d], scaled by 1/rowsum ----
    float* op = out + ((long)b * NQ + i0) * HID + h * DHEAD;
    #pragma unroll
    for (int mt = 0; mt < 2; mt++) {
        int rl = MB + mt * 16 + g;
        #pragma unroll
        for (int nto = 0; nto < 4; nto++) {
            int d = NB2 + nto * 8 + 2 * t4;
            *(float2*)(op + (long)rl * HID + d) =
                make_float2(acco[mt][nto][0] * inv[mt][0], acco[mt][nto][1] * inv[mt][0]);
            *(float2*)(op + (long)(rl + 8) * HID + d) =
                make_float2(acco[mt][nto][2] * inv[mt][1], acco[mt][nto][3] * inv[mt][1]);
        }
    }
}

// ================= launch =================
extern "C" void kernel_launch(void* const* d_in, const int* in_sizes, int n_in,
                              void* d_out, int out_size)
{
    const float* x    = (const float*)d_in[0];
    const float* ctx  = (const float*)d_in[1];
    const float* Wq   = (const float*)d_in[2];
    const float* Wkv  = (const float*)d_in[3];
    const float* Wout = (const float*)d_in[4];
    const float* bout = (const float*)d_in[5];
    float* y = (float*)d_out;

    float *q, *kv, *outb;
    cudaGetSymbolAddress((void**)&q,    g_q);
    cudaGetSymbolAddress((void**)&kv,   g_kv);
    cudaGetSymbolAddress((void**)&outb, g_out);

    cudaFuncSetAttribute(fused_attn, cudaFuncAttributeMaxDynamicSharedMemorySize, FSM_BYTES);

    dim3 blk(256);

    // 1) q = 0.125 * Wq @ x       (M=512,N=4096,K=512) per batch; B=x[c][n] n-contig
    mma_gemm<0><<<dim3(NQ / 128, CCH / 128, BATCH), blk>>>(
        Wq, x, q, nullptr, CCH, NQ, NQ, CCH,
        (long)CCH * NQ, (long)HID * NQ, 0.125f);

    // 2) kv = Wkv @ ctx^T         (M=1024,N=256,K=768) per batch; B=ctx[t][c] k-contig
    mma_gemm<1><<<dim3(TLEN / 128, (2 * HID) / 128, BATCH), blk>>>(
        Wkv, ctx, kv, nullptr, CDIM, CDIM, TLEN, CDIM,
        (long)TLEN * CDIM, (long)2 * HID * TLEN, 1.0f);

    // 3) fused attention: sim + softmax + attn@V -> outb [b][i][hd]
    fused_attn<<<dim3(NQ / 128, BATCH * NHEAD), blk, FSM_BYTES>>>(q, kv, outb);

    // 4) y = Wout @ out + bout    (M=512,N=4096,K=512) per batch; B=outb[i][hd] k-contig
    mma_gemm<1><<<dim3(NQ / 128, CCH / 128, BATCH), blk>>>(
        Wout, outb, y, bout, HID, HID, NQ, HID,
        (long)NQ * HID, (long)CCH * NQ, 1.0f);
}

// round 5
// speedup vs baseline: 6.6955x; 1.6760x over previous
#include <cuda_runtime.h>
#include <cuda_fp16.h>
#include <cstdint>
#include <math.h>

// ---------------- problem dims ----------------
#define BATCH 8
#define CCH   512
#define NQ    4096
#define TLEN  256
#define CDIM  768
#define HID   512
#define NHEAD 8
#define DHEAD 64

// ---------------- scratch ----------------
__device__ float g_q  [(long)BATCH * HID * NQ];       // [b][o=h*64+d][i]
__device__ float g_kv [(long)BATCH * 2 * HID * TLEN]; // [b][o][t]
__device__ float g_out[(long)BATCH * NQ * HID];       // [b][i][hd]

__device__ __forceinline__ uint32_t smem_u32(const void* p) {
    uint32_t a;
    asm("{ .reg .u64 t; cvta.to.shared.u64 t, %1; cvt.u32.u64 %0, t; }" : "=r"(a) : "l"(p));
    return a;
}
__device__ __forceinline__ uint32_t h2(float a, float b) {
    __half2 h = __floats2half2_rn(a, b);
    return *(uint32_t*)&h;
}
__device__ __forceinline__ void ldsm4(uint32_t* r, uint32_t addr) {
    asm volatile("ldmatrix.sync.aligned.m8n8.x4.shared.b16 {%0,%1,%2,%3}, [%4];"
                 : "=r"(r[0]), "=r"(r[1]), "=r"(r[2]), "=r"(r[3]) : "r"(addr));
}
__device__ __forceinline__ void ldsm4t(uint32_t* r, uint32_t addr) {
    asm volatile("ldmatrix.sync.aligned.m8n8.x4.trans.shared.b16 {%0,%1,%2,%3}, [%4];"
                 : "=r"(r[0]), "=r"(r[1]), "=r"(r[2]), "=r"(r[3]) : "r"(addr));
}
__device__ __forceinline__ void mma_f16(float* d, const uint32_t* a, const uint32_t* b) {
    asm volatile(
        "mma.sync.aligned.m16n8k16.row.col.f32.f16.f16.f32 "
        "{%0,%1,%2,%3}, {%4,%5,%6,%7}, {%8,%9}, {%0,%1,%2,%3};"
        : "+f"(d[0]), "+f"(d[1]), "+f"(d[2]), "+f"(d[3])
        : "r"(a[0]), "r"(a[1]), "r"(a[2]), "r"(a[3]), "r"(b[0]), "r"(b[1]));
}

// =====================================================================
// fp16 mma GEMM: C[z][m][n] = alpha * A[m][k] * B(k,n) (+ bias[m])
// A[m][k] k-contig. BDIR=1: B[n][k] k-contig. BDIR=0: B[k][n] n-contig.
// CTA 128x128, BK=32, 8 warps (4x2), warp tile 32x64. ldmatrix fragments.
// =====================================================================
template<int BDIR>
__global__ __launch_bounds__(256, 2) void hgemm(
    const float* __restrict__ A, const float* __restrict__ B,
    float* __restrict__ C, const float* __restrict__ bias,
    int lda, int ldb, int ldc, int kTotal,
    long sB1, long sC1, float alpha)
{
    constexpr int BM = 128, BN = 128, BK = 32;
    constexpr int AS = BK + 8;                    // 40 halves = 80B stride
    constexpr int BS = BDIR ? (BK + 8) : (BN + 8); // 40 or 136
    constexpr int BROWS = BDIR ? BN : BK;

    __shared__ __half Asm[2][BM * AS];
    __shared__ __half Bsm[2][BROWS * BS];

    const int z = blockIdx.z;
    B += (long)z * sB1;
    C += (long)z * sC1;

    const int tid = threadIdx.x;
    const int wid = tid >> 5, lane = tid & 31;
    const int wm = wid & 3, wn = wid >> 2;
    const int g = lane >> 2, t4 = lane & 3;
    const int l8 = lane & 7, l16 = lane & 15;
    const int lhi8 = (lane >> 4) << 3;            // (lane/16)*8
    const int lq8 = ((lane >> 3) & 1) << 3;       // ((lane/8)%2)*8

    const int m0 = blockIdx.y * BM;
    const int n0 = blockIdx.x * BN;
    const int mb = wm * 32, nb = wn * 64;

    const uint32_t Aaddr = smem_u32(&Asm[0][0]);
    const uint32_t Baddr = smem_u32(&Bsm[0][0]);

    float acc[2][8][4];
    #pragma unroll
    for (int i = 0; i < 2; i++)
        #pragma unroll
        for (int j = 0; j < 8; j++)
            #pragma unroll
            for (int r = 0; r < 4; r++) acc[i][j][r] = 0.0f;

    uint2 aH[4], bH[4];

    auto LOADG = [&](int k0) {
        #pragma unroll
        for (int r = 0; r < 4; r++) {
            int f = r * 256 + tid;
            int k4 = f & 7, m = f >> 3;
            float4 v = *(const float4*)(A + (long)(m0 + m) * lda + k0 + k4 * 4);
            aH[r] = make_uint2(h2(v.x, v.y), h2(v.z, v.w));
        }
        #pragma unroll
        for (int r = 0; r < 4; r++) {
            int f = r * 256 + tid;
            float4 v;
            if (BDIR) {
                int k4 = f & 7, n = f >> 3;
                v = *(const float4*)(B + (long)(n0 + n) * ldb + k0 + k4 * 4);
            } else {
                int n4 = f & 31, kk = f >> 5;
                v = *(const float4*)(B + (long)(k0 + kk) * ldb + n0 + n4 * 4);
            }
            bH[r] = make_uint2(h2(v.x, v.y), h2(v.z, v.w));
        }
    };
    auto STORES = [&](int s) {
        #pragma unroll
        for (int r = 0; r < 4; r++) {
            int f = r * 256 + tid;
            int k4 = f & 7, m = f >> 3;
            *(uint2*)&Asm[s][m * AS + k4 * 4] = aH[r];
        }
        #pragma unroll
        for (int r = 0; r < 4; r++) {
            int f = r * 256 + tid;
            if (BDIR) {
                int k4 = f & 7, n = f >> 3;
                *(uint2*)&Bsm[s][n * BS + k4 * 4] = bH[r];
            } else {
                int n4 = f & 31, kk = f >> 5;
                *(uint2*)&Bsm[s][kk * BS + n4 * 4] = bH[r];
            }
        }
    };
    auto COMPUTE = [&](int s) {
        const uint32_t ab = Aaddr + s * (BM * AS * 2);
        const uint32_t bb = Baddr + s * (BROWS * BS * 2);
        #pragma unroll
        for (int ks = 0; ks < 2; ks++) {
            const int kof = ks * 16;
            uint32_t a[2][4];
            ldsm4(a[0], ab + ((mb + l16) * AS + kof + lhi8) * 2);
            ldsm4(a[1], ab + ((mb + 16 + l16) * AS + kof + lhi8) * 2);
            #pragma unroll
            for (int np = 0; np < 4; np++) {
                uint32_t b[4];
                if (BDIR)
                    ldsm4(b, bb + ((nb + np * 16 + lhi8 + l8) * BS + kof + lq8) * 2);
                else
                    ldsm4t(b, bb + ((kof + l16) * BS + nb + np * 16 + lhi8) * 2);
                mma_f16(acc[0][np * 2],     a[0], b);
                mma_f16(acc[1][np * 2],     a[1], b);
                mma_f16(acc[0][np * 2 + 1], a[0], b + 2);
                mma_f16(acc[1][np * 2 + 1], a[1], b + 2);
            }
        }
    };

    const int niter = kTotal / BK;
    LOADG(0);
    STORES(0);
    __syncthreads();
    for (int it = 0; it < niter; it++) {
        if (it + 1 < niter) LOADG((it + 1) * BK);
        COMPUTE(it & 1);
        if (it + 1 < niter) {
            STORES((it + 1) & 1);
            __syncthreads();
        }
    }

    #pragma unroll
    for (int mt = 0; mt < 2; mt++) {
        int m = m0 + mb + mt * 16 + g;
        float bv0 = bias ? bias[m] : 0.0f;
        float bv1 = bias ? bias[m + 8] : 0.0f;
        #pragma unroll
        for (int nt = 0; nt < 8; nt++) {
            int n = n0 + nb + nt * 8 + t4 * 2;
            *(float2*)(C + (long)m * ldc + n) =
                make_float2(acc[mt][nt][0] * alpha + bv0, acc[mt][nt][1] * alpha + bv0);
            *(float2*)(C + (long)(m + 8) * ldc + n) =
                make_float2(acc[mt][nt][2] * alpha + bv1, acc[mt][nt][3] * alpha + bv1);
        }
    }
}

// =====================================================================
// Fused attention (fp16 fragments): per CTA = (b,h) x 128-query tile.
// Q smem [d][i] (A via ldmatrix.trans), K smem [d][j] (B via trans),
// V smem [d][j] (B non-trans over n=d,k=j), P smem [i][j] (A non-trans).
// =====================================================================
#define QS 136
#define KS 264
#define VS 264
#define PS 264
#define OQ 0
#define OKk (OQ + 64 * QS)          // 8704
#define OV  (OKk + 64 * KS)         // 25600
#define OP  (OV + 64 * VS)          // 42496
#define FH_TOTAL (OP + 128 * PS)    // 76288 halves
#define RED_BYTES 2048
#define FSM_BYTES (FH_TOTAL * 2 + RED_BYTES)

__global__ __launch_bounds__(256, 1) void fused_attn(
    const float* __restrict__ q, const float* __restrict__ kv,
    float* __restrict__ out)
{
    extern __shared__ __align__(16) char smraw[];
    __half* sh = (__half*)smraw;
    float* red = (float*)(smraw + FH_TOTAL * 2);

    const int z = blockIdx.y;
    const int b = z >> 3, h = z & 7;
    const int i0 = blockIdx.x * 128;
    const int tid = threadIdx.x;
    const int wid = tid >> 5, lane = tid & 31;
    const int wm = wid & 3, wn = wid >> 2;
    const int g = lane >> 2, t4 = lane & 3;
    const int l8 = lane & 7, l16 = lane & 15;
    const int lhi8 = (lane >> 4) << 3;
    const int lq8 = ((lane >> 3) & 1) << 3;

    const float* qp = q + (long)(b * HID + h * DHEAD) * NQ;
    const float* kp = kv + (long)(b * 2 * HID + h * DHEAD) * TLEN;
    const float* vp = kp + (long)HID * TLEN;

    const uint32_t sbase = smem_u32(sh);

    // ---- load Q (64x128), K,V (64x256), fp32 -> fp16 ----
    #pragma unroll
    for (int r = 0; r < 8; r++) {
        int f = r * 256 + tid;
        int i4 = f & 31, d = f >> 5;
        float4 v = *(const float4*)(qp + (long)d * NQ + i0 + i4 * 4);
        *(uint2*)&sh[OQ + d * QS + i4 * 4] = make_uint2(h2(v.x, v.y), h2(v.z, v.w));
    }
    #pragma unroll
    for (int r = 0; r < 16; r++) {
        int f = r * 256 + tid;
        int j4 = f & 63, d = f >> 6;
        float4 v = *(const float4*)(kp + d * TLEN + j4 * 4);
        *(uint2*)&sh[OKk + d * KS + j4 * 4] = make_uint2(h2(v.x, v.y), h2(v.z, v.w));
        float4 w = *(const float4*)(vp + d * TLEN + j4 * 4);
        *(uint2*)&sh[OV + d * VS + j4 * 4] = make_uint2(h2(w.x, w.y), h2(w.z, w.w));
    }
    __syncthreads();

    const int MB = wm * 32, NB = wn * 128;

    // ---- S = Q^T K : warp tile 32x128, k=d=64 (4 chunks of 16) ----
    float acc[2][16][4];
    #pragma unroll
    for (int i = 0; i < 2; i++)
        #pragma unroll
        for (int j = 0; j < 16; j++)
            #pragma unroll
            for (int r = 0; r < 4; r++) acc[i][j][r] = 0.0f;

    #pragma unroll
    for (int ks = 0; ks < 4; ks++) {
        const int kof = ks * 16;
        uint32_t a[2][4];
        ldsm4t(a[0], sbase + ((OQ) + (kof + lhi8 + l8) * QS + MB + lq8) * 2);
        ldsm4t(a[1], sbase + ((OQ) + (kof + lhi8 + l8) * QS + MB + 16 + lq8) * 2);
        #pragma unroll
        for (int np = 0; np < 8; np++) {
            uint32_t bfr[4];
            ldsm4t(bfr, sbase + ((OKk) + (kof + l16) * KS + NB + np * 16 + lhi8) * 2);
            mma_f16(acc[0][np * 2],     a[0], bfr);
            mma_f16(acc[1][np * 2],     a[1], bfr);
            mma_f16(acc[0][np * 2 + 1], a[0], bfr + 2);
            mma_f16(acc[1][np * 2 + 1], a[1], bfr + 2);
        }
    }

    // ---- softmax: row max ----
    float* redm = red;         // [2][128]
    float* reds = red + 256;   // [2][128]
    float rmx[2][2], rsm[2][2], inv[2][2];
    #pragma unroll
    for (int mt = 0; mt < 2; mt++)
        #pragma unroll
        for (int u = 0; u < 2; u++) {
            float m = -INFINITY;
            #pragma unroll
            for (int nt = 0; nt < 16; nt++)
                m = fmaxf(m, fmaxf(acc[mt][nt][2 * u], acc[mt][nt][2 * u + 1]));
            m = fmaxf(m, __shfl_xor_sync(0xffffffffu, m, 1));
            m = fmaxf(m, __shfl_xor_sync(0xffffffffu, m, 2));
            if (t4 == 0) redm[wn * 128 + wm * 32 + mt * 16 + u * 8 + g] = m;
        }
    __syncthreads();
    #pragma unroll
    for (int mt = 0; mt < 2; mt++)
        #pragma unroll
        for (int u = 0; u < 2; u++) {
            int r = wm * 32 + mt * 16 + u * 8 + g;
            rmx[mt][u] = fmaxf(redm[r], redm[128 + r]);
            rsm[mt][u] = 0.0f;
        }

    // ---- exp, row-sum, stage P (unnormalized fp16) ----
    #pragma unroll
    for (int mt = 0; mt < 2; mt++) {
        int row = MB + mt * 16 + g;
        #pragma unroll
        for (int nt = 0; nt < 16; nt++) {
            int col = NB + nt * 8 + 2 * t4;
            float e0 = __expf(acc[mt][nt][0] - rmx[mt][0]);
            float e1 = __expf(acc[mt][nt][1] - rmx[mt][0]);
            float e2 = __expf(acc[mt][nt][2] - rmx[mt][1]);
            float e3 = __expf(acc[mt][nt][3] - rmx[mt][1]);
            rsm[mt][0] += e0 + e1;
            rsm[mt][1] += e2 + e3;
            *(uint32_t*)&sh[OP + row * PS + col] = h2(e0, e1);
            *(uint32_t*)&sh[OP + (row + 8) * PS + col] = h2(e2, e3);
        }
    }
    #pragma unroll
    for (int mt = 0; mt < 2; mt++)
        #pragma unroll
        for (int u = 0; u < 2; u++) {
            float s = rsm[mt][u];
            s += __shfl_xor_sync(0xffffffffu, s, 1);
            s += __shfl_xor_sync(0xffffffffu, s, 2);
            if (t4 == 0) reds[wn * 128 + wm * 32 + mt * 16 + u * 8 + g] = s;
        }
    __syncthreads();
    #pragma unroll
    for (int mt = 0; mt < 2; mt++)
        #pragma unroll
        for (int u = 0; u < 2; u++) {
            int r = wm * 32 + mt * 16 + u * 8 + g;
            inv[mt][u] = 1.0f / (reds[r] + reds[128 + r]);
        }

    // ---- O = P V : warp tile 32x32, k=j=256 (16 chunks) ----
    const int NB2 = wn * 32;
    float acco[2][4][4];
    #pragma unroll
    for (int i = 0; i < 2; i++)
        #pragma unroll
        for (int j = 0; j < 4; j++)
            #pragma unroll
            for (int r = 0; r < 4; r++) acco[i][j][r] = 0.0f;

    #pragma unroll
    for (int ks = 0; ks < 16; ks++) {
        const int kof = ks * 16;
        uint32_t a[2][4];
        ldsm4(a[0], sbase + ((OP) + (MB + l16) * PS + kof + lhi8) * 2);
        ldsm4(a[1], sbase + ((OP) + (MB + 16 + l16) * PS + kof + lhi8) * 2);
        #pragma unroll
        for (int np = 0; np < 2; np++) {
            uint32_t bfr[4];
            ldsm4(bfr, sbase + ((OV) + (NB2 + np * 16 + lhi8 + l8) * VS + kof + lq8) * 2);
            mma_f16(acco[0][np * 2],     a[0], bfr);
            mma_f16(acco[1][np * 2],     a[1], bfr);
            mma_f16(acco[0][np * 2 + 1], a[0], bfr + 2);
            mma_f16(acco[1][np * 2 + 1], a[1], bfr + 2);
        }
    }

    // ---- store O[b][i0+i][h*64+d] scaled ----
    float* op = out + ((long)b * NQ + i0) * HID + h * DHEAD;
    #pragma unroll
    for (int mt = 0; mt < 2; mt++) {
        int rl = MB + mt * 16 + g;
        #pragma unroll
        for (int nt = 0; nt < 4; nt++) {
            int d = NB2 + nt * 8 + 2 * t4;
            *(float2*)(op + (long)rl * HID + d) =
                make_float2(acco[mt][nt][0] * inv[mt][0], acco[mt][nt][1] * inv[mt][0]);
            *(float2*)(op + (long)(rl + 8) * HID + d) =
                make_float2(acco[mt][nt][2] * inv[mt][1], acco[mt][nt][3] * inv[mt][1]);
        }
    }
}

// ================= launch =================
extern "C" void kernel_launch(void* const* d_in, const int* in_sizes, int n_in,
                              void* d_out, int out_size)
{
    const float* x    = (const float*)d_in[0];
    const float* ctx  = (const float*)d_in[1];
    const float* Wq   = (const float*)d_in[2];
    const float* Wkv  = (const float*)d_in[3];
    const float* Wout = (const float*)d_in[4];
    const float* bout = (const float*)d_in[5];
    float* y = (float*)d_out;

    float *q, *kv, *outb;
    cudaGetSymbolAddress((void**)&q,    g_q);
    cudaGetSymbolAddress((void**)&kv,   g_kv);
    cudaGetSymbolAddress((void**)&outb, g_out);

    cudaFuncSetAttribute(fused_attn, cudaFuncAttributeMaxDynamicSharedMemorySize, FSM_BYTES);

    dim3 blk(256);

    // 1) q = 0.125 * Wq @ x     (M=512,N=4096,K=512)/batch; B=x[c][n] n-contig
    hgemm<0><<<dim3(NQ / 128, CCH / 128, BATCH), blk>>>(
        Wq, x, q, nullptr, CCH, NQ, NQ, CCH,
        (long)CCH * NQ, (long)HID * NQ, 0.125f);

    // 2) kv = Wkv @ ctx^T       (M=1024,N=256,K=768)/batch; B=ctx[t][c] k-contig
    hgemm<1><<<dim3(TLEN / 128, (2 * HID) / 128, BATCH), blk>>>(
        Wkv, ctx, kv, nullptr, CDIM, CDIM, TLEN, CDIM,
        (long)TLEN * CDIM, (long)2 * HID * TLEN, 1.0f);

    // 3) fused attention -> outb [b][i][hd]
    fused_attn<<<dim3(NQ / 128, BATCH * NHEAD), blk, FSM_BYTES>>>(q, kv, outb);

    // 4) y = Wout @ out + bout  (M=512,N=4096,K=512)/batch; B=outb[i][hd] k-contig
    hgemm<1><<<dim3(NQ / 128, CCH / 128, BATCH), blk>>>(
        Wout, outb, y, bout, HID, HID, NQ, HID,
        (long)NQ * HID, (long)CCH * NQ, 1.0f);
}

// round 6
// speedup vs baseline: 7.9782x; 1.1916x over previous
#include <cuda_runtime.h>
#include <cuda_fp16.h>
#include <cstdint>
#include <math.h>

// ---------------- problem dims ----------------
#define BATCH 8
#define CCH   512
#define NQ    4096
#define TLEN  256
#define CDIM  768
#define HID   512
#define NHEAD 8
#define DHEAD 64

// ---------------- scratch ----------------
__device__ __half g_xh  [(long)BATCH * CCH * NQ];
__device__ __half g_ctxh[(long)BATCH * TLEN * CDIM];
__device__ __half g_Wqh [HID * CCH];
__device__ __half g_Wkvh[2 * HID * CDIM];
__device__ __half g_Wouth[CCH * HID];
__device__ __half g_q   [(long)BATCH * HID * NQ];        // [b][o][i]
__device__ __half g_kv  [(long)BATCH * 2 * HID * TLEN];  // [b][o][t]
__device__ __half g_out [(long)BATCH * NQ * HID];        // [b][i][hd]

__device__ __forceinline__ uint32_t smem_u32(const void* p) {
    uint32_t a;
    asm("{ .reg .u64 t; cvta.to.shared.u64 t, %1; cvt.u32.u64 %0, t; }" : "=r"(a) : "l"(p));
    return a;
}
__device__ __forceinline__ uint32_t h2(float a, float b) {
    __half2 h = __floats2half2_rn(a, b);
    return *(uint32_t*)&h;
}
__device__ __forceinline__ void cpa16(uint32_t dst, const void* src) {
    asm volatile("cp.async.cg.shared.global [%0], [%1], 16;" :: "r"(dst), "l"(src));
}
#define CP_COMMIT() asm volatile("cp.async.commit_group;" ::: "memory")
template<int N> __device__ __forceinline__ void cp_wait() {
    asm volatile("cp.async.wait_group %0;" :: "n"(N) : "memory");
}
__device__ __forceinline__ void ldsm4(uint32_t* r, uint32_t addr) {
    asm volatile("ldmatrix.sync.aligned.m8n8.x4.shared.b16 {%0,%1,%2,%3}, [%4];"
                 : "=r"(r[0]), "=r"(r[1]), "=r"(r[2]), "=r"(r[3]) : "r"(addr));
}
__device__ __forceinline__ void ldsm4t(uint32_t* r, uint32_t addr) {
    asm volatile("ldmatrix.sync.aligned.m8n8.x4.trans.shared.b16 {%0,%1,%2,%3}, [%4];"
                 : "=r"(r[0]), "=r"(r[1]), "=r"(r[2]), "=r"(r[3]) : "r"(addr));
}
__device__ __forceinline__ void mma_f16(float* d, const uint32_t* a, const uint32_t* b) {
    asm volatile(
        "mma.sync.aligned.m16n8k16.row.col.f32.f16.f16.f32 "
        "{%0,%1,%2,%3}, {%4,%5,%6,%7}, {%8,%9}, {%0,%1,%2,%3};"
        : "+f"(d[0]), "+f"(d[1]), "+f"(d[2]), "+f"(d[3])
        : "r"(a[0]), "r"(a[1]), "r"(a[2]), "r"(a[3]), "r"(b[0]), "r"(b[1]));
}

// ---------------- fp32 -> fp16 conversion ----------------
__global__ __launch_bounds__(256) void f2h_kernel(
    const float4* __restrict__ in, uint2* __restrict__ out, int n4)
{
    int i = blockIdx.x * 256 + threadIdx.x;
    if (i < n4) {
        float4 v = in[i];
        out[i] = make_uint2(h2(v.x, v.y), h2(v.z, v.w));
    }
}

// =====================================================================
// fp16 mma GEMM with cp.async, 3 stages:
//   C[z][m][n] = alpha * A[m][k] * B(k,n) (+ bias[m])
// A[m][k] k-contig. BDIR=1: B[n][k] k-contig. BDIR=0: B[k][n] n-contig.
// CTA 128x128, BK=32, 8 warps (4x2), warp tile 32x64.
// =====================================================================
template<int BDIR, typename CT>
__global__ __launch_bounds__(256, 2) void hgemm(
    const __half* __restrict__ A, const __half* __restrict__ B,
    CT* __restrict__ C, const float* __restrict__ bias,
    int lda, int ldb, int ldc, int kTotal,
    long sB1, long sC1, float alpha)
{
    constexpr int BM = 128, BN = 128, BK = 32;
    constexpr int AS = BK + 8;                      // 40 halves (80B, 16B-mult)
    constexpr int BS = BDIR ? (BK + 8) : (BN + 8);  // 40 or 136
    constexpr int BROWS = BDIR ? BN : BK;
    constexpr int ASTG = BM * AS;                   // halves per A stage
    constexpr int BSTG = BROWS * BS;

    extern __shared__ __half sm[];
    __half* Asm = sm;                 // 3 stages
    __half* Bsm = sm + 3 * ASTG;

    const int z = blockIdx.z;
    B += (long)z * sB1;
    C += (long)z * sC1;

    const int tid = threadIdx.x;
    const int wid = tid >> 5, lane = tid & 31;
    const int wm = wid & 3, wn = wid >> 2;
    const int g = lane >> 2, t4 = lane & 3;
    const int l8 = lane & 7, l16 = lane & 15;
    const int lhi8 = (lane >> 4) << 3;
    const int lq8 = ((lane >> 3) & 1) << 3;

    const int m0 = blockIdx.y * BM;
    const int n0 = blockIdx.x * BN;
    const int mb = wm * 32, nb = wn * 64;

    const uint32_t Aaddr = smem_u32(Asm);
    const uint32_t Baddr = smem_u32(Bsm);

    float acc[2][8][4];
    #pragma unroll
    for (int i = 0; i < 2; i++)
        #pragma unroll
        for (int j = 0; j < 8; j++)
            #pragma unroll
            for (int r = 0; r < 4; r++) acc[i][j][r] = 0.0f;

    // issue cp.async loads for k-chunk into stage s
    auto LOADS = [&](int s, int k0) {
        uint32_t ab = Aaddr + s * (ASTG * 2);
        uint32_t bb = Baddr + s * (BSTG * 2);
        #pragma unroll
        for (int r = 0; r < 2; r++) {
            int f = r * 256 + tid;
            int k8 = f & 3, m = f >> 2;
            cpa16(ab + (m * AS + k8 * 8) * 2, A + (long)(m0 + m) * lda + k0 + k8 * 8);
        }
        #pragma unroll
        for (int r = 0; r < 2; r++) {
            int f = r * 256 + tid;
            if (BDIR) {
                int k8 = f & 3, n = f >> 2;
                cpa16(bb + (n * BS + k8 * 8) * 2, B + (long)(n0 + n) * ldb + k0 + k8 * 8);
            } else {
                int n8 = f & 15, kk = f >> 4;
                cpa16(bb + (kk * BS + n8 * 8) * 2, B + (long)(k0 + kk) * ldb + n0 + n8 * 8);
            }
        }
    };
    auto COMPUTE = [&](int s) {
        const uint32_t ab = Aaddr + s * (ASTG * 2);
        const uint32_t bb = Baddr + s * (BSTG * 2);
        #pragma unroll
        for (int ks = 0; ks < 2; ks++) {
            const int kof = ks * 16;
            uint32_t a[2][4];
            ldsm4(a[0], ab + ((mb + l16) * AS + kof + lhi8) * 2);
            ldsm4(a[1], ab + ((mb + 16 + l16) * AS + kof + lhi8) * 2);
            #pragma unroll
            for (int np = 0; np < 4; np++) {
                uint32_t b[4];
                if (BDIR)
                    ldsm4(b, bb + ((nb + np * 16 + lhi8 + l8) * BS + kof + lq8) * 2);
                else
                    ldsm4t(b, bb + ((kof + l16) * BS + nb + np * 16 + lhi8) * 2);
                mma_f16(acc[0][np * 2],     a[0], b);
                mma_f16(acc[1][np * 2],     a[1], b);
                mma_f16(acc[0][np * 2 + 1], a[0], b + 2);
                mma_f16(acc[1][np * 2 + 1], a[1], b + 2);
            }
        }
    };

    const int niter = kTotal / BK;
    LOADS(0, 0);
    CP_COMMIT();
    LOADS(1, BK);
    CP_COMMIT();
    cp_wait<1>();
    __syncthreads();

    for (int it = 0; it < niter; it++) {
        COMPUTE(it % 3);
        if (it + 2 < niter) {
            LOADS((it + 2) % 3, (it + 2) * BK);
            CP_COMMIT();
            cp_wait<1>();
        } else if (it + 1 < niter) {
            cp_wait<0>();
        }
        if (it + 1 < niter) __syncthreads();
    }

    #pragma unroll
    for (int mt = 0; mt < 2; mt++) {
        int m = m0 + mb + mt * 16 + g;
        float bv0 = bias ? bias[m] : 0.0f;
        float bv1 = bias ? bias[m + 8] : 0.0f;
        #pragma unroll
        for (int nt = 0; nt < 8; nt++) {
            int n = n0 + nb + nt * 8 + t4 * 2;
            if (sizeof(CT) == 4) {
                *(float2*)((float*)C + (long)m * ldc + n) =
                    make_float2(acc[mt][nt][0] * alpha + bv0, acc[mt][nt][1] * alpha + bv0);
                *(float2*)((float*)C + (long)(m + 8) * ldc + n) =
                    make_float2(acc[mt][nt][2] * alpha + bv1, acc[mt][nt][3] * alpha + bv1);
            } else {
                *(uint32_t*)((__half*)C + (long)m * ldc + n) =
                    h2(acc[mt][nt][0] * alpha + bv0, acc[mt][nt][1] * alpha + bv0);
                *(uint32_t*)((__half*)C + (long)(m + 8) * ldc + n) =
                    h2(acc[mt][nt][2] * alpha + bv1, acc[mt][nt][3] * alpha + bv1);
            }
        }
    }
}

// =====================================================================
// Fused attention (fp16 in/out): per CTA = (b,h) x 128-query tile.
// =====================================================================
#define QS 136
#define KS 264
#define VS 264
#define PS 264
#define OQ 0
#define OKk (OQ + 64 * QS)
#define OV  (OKk + 64 * KS)
#define OP  (OV + 64 * VS)
#define FH_TOTAL (OP + 128 * PS)
#define RED_BYTES 2048
#define FSM_BYTES (FH_TOTAL * 2 + RED_BYTES)

__global__ __launch_bounds__(256, 1) void fused_attn(
    const __half* __restrict__ q, const __half* __restrict__ kv,
    __half* __restrict__ out)
{
    extern __shared__ __align__(16) char smraw[];
    __half* sh = (__half*)smraw;
    float* red = (float*)(smraw + FH_TOTAL * 2);

    const int z = blockIdx.y;
    const int b = z >> 3, h = z & 7;
    const int i0 = blockIdx.x * 128;
    const int tid = threadIdx.x;
    const int wid = tid >> 5, lane = tid & 31;
    const int wm = wid & 3, wn = wid >> 2;
    const int g = lane >> 2, t4 = lane & 3;
    const int l8 = lane & 7, l16 = lane & 15;
    const int lhi8 = (lane >> 4) << 3;
    const int lq8 = ((lane >> 3) & 1) << 3;

    const __half* qp = q + (long)(b * HID + h * DHEAD) * NQ;
    const __half* kp = kv + (long)(b * 2 * HID + h * DHEAD) * TLEN;
    const __half* vp = kp + (long)HID * TLEN;

    const uint32_t sbase = smem_u32(sh);

    // ---- async loads: Q 64x128, K,V 64x256 (fp16) ----
    #pragma unroll
    for (int r = 0; r < 4; r++) {
        int f = r * 256 + tid;
        int i8 = f & 15, d = f >> 4;
        cpa16(sbase + (OQ + d * QS + i8 * 8) * 2, qp + (long)d * NQ + i0 + i8 * 8);
    }
    #pragma unroll
    for (int r = 0; r < 8; r++) {
        int f = r * 256 + tid;
        int j8 = f & 31, d = f >> 5;
        cpa16(sbase + (OKk + d * KS + j8 * 8) * 2, kp + d * TLEN + j8 * 8);
        cpa16(sbase + (OV + d * VS + j8 * 8) * 2, vp + d * TLEN + j8 * 8);
    }
    CP_COMMIT();
    cp_wait<0>();
    __syncthreads();

    const int MB = wm * 32, NB = wn * 128;

    // ---- S = Q^T K ----
    float acc[2][16][4];
    #pragma unroll
    for (int i = 0; i < 2; i++)
        #pragma unroll
        for (int j = 0; j < 16; j++)
            #pragma unroll
            for (int r = 0; r < 4; r++) acc[i][j][r] = 0.0f;

    #pragma unroll
    for (int ks = 0; ks < 4; ks++) {
        const int kof = ks * 16;
        uint32_t a[2][4];
        ldsm4t(a[0], sbase + (OQ + (kof + lhi8 + l8) * QS + MB + lq8) * 2);
        ldsm4t(a[1], sbase + (OQ + (kof + lhi8 + l8) * QS + MB + 16 + lq8) * 2);
        #pragma unroll
        for (int np = 0; np < 8; np++) {
            uint32_t bfr[4];
            ldsm4t(bfr, sbase + (OKk + (kof + l16) * KS + NB + np * 16 + lhi8) * 2);
            mma_f16(acc[0][np * 2],     a[0], bfr);
            mma_f16(acc[1][np * 2],     a[1], bfr);
            mma_f16(acc[0][np * 2 + 1], a[0], bfr + 2);
            mma_f16(acc[1][np * 2 + 1], a[1], bfr + 2);
        }
    }

    // ---- softmax: row max ----
    float* redm = red;
    float* reds = red + 256;
    float rmx[2][2], rsm[2][2], inv[2][2];
    #pragma unroll
    for (int mt = 0; mt < 2; mt++)
        #pragma unroll
        for (int u = 0; u < 2; u++) {
            float m = -INFINITY;
            #pragma unroll
            for (int nt = 0; nt < 16; nt++)
                m = fmaxf(m, fmaxf(acc[mt][nt][2 * u], acc[mt][nt][2 * u + 1]));
            m = fmaxf(m, __shfl_xor_sync(0xffffffffu, m, 1));
            m = fmaxf(m, __shfl_xor_sync(0xffffffffu, m, 2));
            if (t4 == 0) redm[wn * 128 + wm * 32 + mt * 16 + u * 8 + g] = m;
        }
    __syncthreads();
    #pragma unroll
    for (int mt = 0; mt < 2; mt++)
        #pragma unroll
        for (int u = 0; u < 2; u++) {
            int r = wm * 32 + mt * 16 + u * 8 + g;
            rmx[mt][u] = fmaxf(redm[r], redm[128 + r]);
            rsm[mt][u] = 0.0f;
        }

    // ---- exp, row-sum, stage P (fp16, unnormalized) ----
    #pragma unroll
    for (int mt = 0; mt < 2; mt++) {
        int row = MB + mt * 16 + g;
        #pragma unroll
        for (int nt = 0; nt < 16; nt++) {
            int col = NB + nt * 8 + 2 * t4;
            float e0 = __expf(acc[mt][nt][0] - rmx[mt][0]);
            float e1 = __expf(acc[mt][nt][1] - rmx[mt][0]);
            float e2 = __expf(acc[mt][nt][2] - rmx[mt][1]);
            float e3 = __expf(acc[mt][nt][3] - rmx[mt][1]);
            rsm[mt][0] += e0 + e1;
            rsm[mt][1] += e2 + e3;
            *(uint32_t*)&sh[OP + row * PS + col] = h2(e0, e1);
            *(uint32_t*)&sh[OP + (row + 8) * PS + col] = h2(e2, e3);
        }
    }
    #pragma unroll
    for (int mt = 0; mt < 2; mt++)
        #pragma unroll
        for (int u = 0; u < 2; u++) {
            float s = rsm[mt][u];
            s += __shfl_xor_sync(0xffffffffu, s, 1);
            s += __shfl_xor_sync(0xffffffffu, s, 2);
            if (t4 == 0) reds[wn * 128 + wm * 32 + mt * 16 + u * 8 + g] = s;
        }
    __syncthreads();
    #pragma unroll
    for (int mt = 0; mt < 2; mt++)
        #pragma unroll
        for (int u = 0; u < 2; u++) {
            int r = wm * 32 + mt * 16 + u * 8 + g;
            inv[mt][u] = 1.0f / (reds[r] + reds[128 + r]);
        }

    // ---- O = P V ----
    const int NB2 = wn * 32;
    float acco[2][4][4];
    #pragma unroll
    for (int i = 0; i < 2; i++)
        #pragma unroll
        for (int j = 0; j < 4; j++)
            #pragma unroll
            for (int r = 0; r < 4; r++) acco[i][j][r] = 0.0f;

    #pragma unroll
    for (int ks = 0; ks < 16; ks++) {
        const int kof = ks * 16;
        uint32_t a[2][4];
        ldsm4(a[0], sbase + (OP + (MB + l16) * PS + kof + lhi8) * 2);
        ldsm4(a[1], sbase + (OP + (MB + 16 + l16) * PS + kof + lhi8) * 2);
        #pragma unroll
        for (int np = 0; np < 2; np++) {
            uint32_t bfr[4];
            ldsm4(bfr, sbase + (OV + (NB2 + np * 16 + lhi8 + l8) * VS + kof + lq8) * 2);
            mma_f16(acco[0][np * 2],     a[0], bfr);
            mma_f16(acco[1][np * 2],     a[1], bfr);
            mma_f16(acco[0][np * 2 + 1], a[0], bfr + 2);
            mma_f16(acco[1][np * 2 + 1], a[1], bfr + 2);
        }
    }

    // ---- store O (fp16) ----
    __half* op = out + ((long)b * NQ + i0) * HID + h * DHEAD;
    #pragma unroll
    for (int mt = 0; mt < 2; mt++) {
        int rl = MB + mt * 16 + g;
        #pragma unroll
        for (int nt = 0; nt < 4; nt++) {
            int d = NB2 + nt * 8 + 2 * t4;
            *(uint32_t*)(op + (long)rl * HID + d) =
                h2(acco[mt][nt][0] * inv[mt][0], acco[mt][nt][1] * inv[mt][0]);
            *(uint32_t*)(op + (long)(rl + 8) * HID + d) =
                h2(acco[mt][nt][2] * inv[mt][1], acco[mt][nt][3] * inv[mt][1]);
        }
    }
}

// ================= launch =================
extern "C" void kernel_launch(void* const* d_in, const int* in_sizes, int n_in,
                              void* d_out, int out_size)
{
    const float* x    = (const float*)d_in[0];
    const float* ctx  = (const float*)d_in[1];
    const float* Wq   = (const float*)d_in[2];
    const float* Wkv  = (const float*)d_in[3];
    const float* Wout = (const float*)d_in[4];
    const float* bout = (const float*)d_in[5];
    float* y = (float*)d_out;

    __half *xh, *ctxh, *Wqh, *Wkvh, *Wouth, *q, *kv, *outb;
    cudaGetSymbolAddress((void**)&xh,    g_xh);
    cudaGetSymbolAddress((void**)&ctxh,  g_ctxh);
    cudaGetSymbolAddress((void**)&Wqh,   g_Wqh);
    cudaGetSymbolAddress((void**)&Wkvh,  g_Wkvh);
    cudaGetSymbolAddress((void**)&Wouth, g_Wouth);
    cudaGetSymbolAddress((void**)&q,     g_q);
    cudaGetSymbolAddress((void**)&kv,    g_kv);
    cudaGetSymbolAddress((void**)&outb,  g_out);

    constexpr int SM_B1 = 3 * (128 * 40 + 128 * 40) * 2;  // 61440
    constexpr int SM_B0 = 3 * (128 * 40 + 32 * 136) * 2;  // 56832

    cudaFuncSetAttribute((const void*)hgemm<0, __half>, cudaFuncAttributeMaxDynamicSharedMemorySize, SM_B0);
    cudaFuncSetAttribute((const void*)hgemm<1, __half>, cudaFuncAttributeMaxDynamicSharedMemorySize, SM_B1);
    cudaFuncSetAttribute((const void*)hgemm<1, float>,  cudaFuncAttributeMaxDynamicSharedMemorySize, SM_B1);
    cudaFuncSetAttribute((const void*)fused_attn,       cudaFuncAttributeMaxDynamicSharedMemorySize, FSM_BYTES);

    dim3 blk(256);

    // 0) fp32 -> fp16 conversions
    {
        long nx = (long)BATCH * CCH * NQ / 4;
        f2h_kernel<<<(int)((nx + 255) / 256), blk>>>((const float4*)x, (uint2*)xh, (int)nx);
        long nc = (long)BATCH * TLEN * CDIM / 4;
        f2h_kernel<<<(int)((nc + 255) / 256), blk>>>((const float4*)ctx, (uint2*)ctxh, (int)nc);
        int nq_ = HID * CCH / 4;
        f2h_kernel<<<(nq_ + 255) / 256, blk>>>((const float4*)Wq, (uint2*)Wqh, nq_);
        int nk = 2 * HID * CDIM / 4;
        f2h_kernel<<<(nk + 255) / 256, blk>>>((const float4*)Wkv, (uint2*)Wkvh, nk);
        int no = CCH * HID / 4;
        f2h_kernel<<<(no + 255) / 256, blk>>>((const float4*)Wout, (uint2*)Wouth, no);
    }

    // 1) q = 0.125 * Wq @ x    (M=512,N=4096,K=512)/batch; B=xh[c][n] n-contig
    hgemm<0, __half><<<dim3(NQ / 128, CCH / 128, BATCH), blk, SM_B0>>>(
        Wqh, xh, q, nullptr, CCH, NQ, NQ, CCH,
        (long)CCH * NQ, (long)HID * NQ, 0.125f);

    // 2) kv = Wkv @ ctx^T      (M=1024,N=256,K=768)/batch; B=ctxh[t][c] k-contig
    hgemm<1, __half><<<dim3(TLEN / 128, (2 * HID) / 128, BATCH), blk, SM_B1>>>(
        Wkvh, ctxh, kv, nullptr, CDIM, CDIM, TLEN, CDIM,
        (long)TLEN * CDIM, (long)2 * HID * TLEN, 1.0f);

    // 3) fused attention -> outb [b][i][hd] fp16
    fused_attn<<<dim3(NQ / 128, BATCH * NHEAD), blk, FSM_BYTES>>>(q, kv, outb);

    // 4) y = Wout @ out + bout (M=512,N=4096,K=512)/batch; B=outb[i][hd] k-contig
    hgemm<1, float><<<dim3(NQ / 128, CCH / 128, BATCH), blk, SM_B1>>>(
        Wouth, outb, y, bout, HID, HID, NQ, HID,
        (long)NQ * HID, (long)CCH * NQ, 1.0f);
}